// round 5
// baseline (speedup 1.0000x reference)
#include <cuda_runtime.h>

#define T_STEPS 2048
#define BATCH   256
#define DIN     128
#define NG      16      // 4 gates * 4 units; scratch layout k = u*4 + g
#define RDEPTH  2

// Scratch: x-part projections (+bias+theta folded), layout [t][b][u*4+g]
// Over-allocated by RDEPTH steps so the recurrence prefetch needs no bounds check.
__device__ float g_xproj[(T_STEPS + RDEPTH) * BATCH * NG];

// ---------------------------------------------------------------------------
// Kernel 1: fused 4-gate projection
// ---------------------------------------------------------------------------
#define TILE_ROWS    64
#define PROJ_THREADS 256

__global__ __launch_bounds__(PROJ_THREADS)
void proj_kernel(const float* __restrict__ x,
                 const float* __restrict__ Wf, const float* __restrict__ bf, const float* __restrict__ thf,
                 const float* __restrict__ Wi, const float* __restrict__ bi, const float* __restrict__ thi,
                 const float* __restrict__ Wu, const float* __restrict__ bu, const float* __restrict__ thu,
                 const float* __restrict__ Wo, const float* __restrict__ bo, const float* __restrict__ tho)
{
    __shared__ float xs[TILE_ROWS][132];
    __shared__ float ws[DIN][NG];          // ws[j][u*4+g]
    __shared__ float bt[NG];

    const int tid = threadIdx.x;
    const long rowBase = (long)blockIdx.x * TILE_ROWS;

    const float4* x4 = (const float4*)x + rowBase * (DIN / 4);
    #pragma unroll
    for (int i = tid; i < TILE_ROWS * (DIN / 4); i += PROJ_THREADS) {
        float4 v = x4[i];
        int row = i >> 5;
        int c4  = i & 31;
        *(float4*)&xs[row][c4 * 4] = v;
    }
    for (int i = tid; i < DIN * NG; i += PROJ_THREADS) {
        int j = i >> 4, k = i & 15;
        int u = k >> 2, g = k & 3;
        const float* W = (g == 0) ? Wf : (g == 1) ? Wi : (g == 2) ? Wu : Wo;
        ws[j][k] = W[j * 4 + u];
    }
    if (tid < NG) {
        int u = tid >> 2, g = tid & 3;
        const float* b  = (g == 0) ? bf  : (g == 1) ? bi  : (g == 2) ? bu  : bo;
        const float* th = (g == 0) ? thf : (g == 1) ? thi : (g == 2) ? thu : tho;
        bt[tid] = b[u] + th[u];
    }
    __syncthreads();

    const int r  = tid & (TILE_ROWS - 1);
    const int kg = tid >> 6;
    float a0 = 0.f, a1 = 0.f, a2 = 0.f, a3 = 0.f;

    #pragma unroll
    for (int jj = 0; jj < DIN / 4; jj++) {
        float4 xv = *(const float4*)&xs[r][jj * 4];
        float4 w0 = *(const float4*)&ws[jj * 4 + 0][kg * 4];
        float4 w1 = *(const float4*)&ws[jj * 4 + 1][kg * 4];
        float4 w2 = *(const float4*)&ws[jj * 4 + 2][kg * 4];
        float4 w3 = *(const float4*)&ws[jj * 4 + 3][kg * 4];
        a0 = fmaf(xv.x, w0.x, fmaf(xv.y, w1.x, fmaf(xv.z, w2.x, fmaf(xv.w, w3.x, a0))));
        a1 = fmaf(xv.x, w0.y, fmaf(xv.y, w1.y, fmaf(xv.z, w2.y, fmaf(xv.w, w3.y, a1))));
        a2 = fmaf(xv.x, w0.z, fmaf(xv.y, w1.z, fmaf(xv.z, w2.z, fmaf(xv.w, w3.z, a2))));
        a3 = fmaf(xv.x, w0.w, fmaf(xv.y, w1.w, fmaf(xv.z, w2.w, fmaf(xv.w, w3.w, a3))));
    }
    float4 o;
    o.x = a0 + bt[kg * 4 + 0];
    o.y = a1 + bt[kg * 4 + 1];
    o.z = a2 + bt[kg * 4 + 2];
    o.w = a3 + bt[kg * 4 + 3];
    *(float4*)&g_xproj[(rowBase + r) * NG + kg * 4] = o;
}

// ---------------------------------------------------------------------------
// Kernel 2: recurrence; 4 lanes per batch element, 2 independent chains/lane
// ---------------------------------------------------------------------------
// sigmoid on [-1,1] via odd Taylor poly (err <= ~3e-6) -- FMA pipe only
__device__ __forceinline__ float sigp(float xv) {
    float x2 = xv * xv;
    float t = fmaf(x2, 2.135765e-5f, -2.1081349e-4f);
    t = fmaf(x2, t, 2.0833333e-3f);
    t = fmaf(x2, t, -2.0833333e-2f);
    t = fmaf(x2, t, 0.25f);
    return fmaf(xv, t, 0.5f);
}
// tanh via continued-fraction rational, err < ~1e-5 for |x| <= 2.2; 1 MUFU.RCP
__device__ __forceinline__ float tanh_cf_fast(float xv) {
    float t = xv * xv;
    float num = fmaf(t, fmaf(t, 21.0f, 1260.0f), 10395.0f);
    float den = fmaf(t, fmaf(t, fmaf(t, 1.0f, 210.0f), 4725.0f), 10395.0f);
    return __fdividef(xv * num, den);
}

struct Chain {
    float h0, h1, h2, h3, c;
    const float4* xp;        // per-(b,u) stream into g_xproj
    float4 buf[RDEPTH];
};

// One recurrence step for one chain. All cross-lane ops use width-4 groups.
__device__ __forceinline__ void chain_step(Chain& S, int t, int slot,
                                           const float (&Whl)[4][4],
                                           bool ge1, bool ge2, bool ge3,
                                           float& hu_out)
{
    float4 zx = S.buf[slot];
    S.buf[slot] = S.xp[(size_t)(t + RDEPTH) * (BATCH * 4)];

    // z_g = zx_g + h . Whl[:,g] (tree form) then cos
    float a, bb;
    a  = fmaf(S.h1, Whl[1][0], fmaf(S.h0, Whl[0][0], zx.x));
    bb = fmaf(S.h3, Whl[3][0], S.h2 * Whl[2][0]);
    float q0 = __cosf(a + bb);
    a  = fmaf(S.h1, Whl[1][1], fmaf(S.h0, Whl[0][1], zx.y));
    bb = fmaf(S.h3, Whl[3][1], S.h2 * Whl[2][1]);
    float q1 = __cosf(a + bb);
    a  = fmaf(S.h1, Whl[1][2], fmaf(S.h0, Whl[0][2], zx.z));
    bb = fmaf(S.h3, Whl[3][2], S.h2 * Whl[2][2]);
    float q2 = __cosf(a + bb);
    a  = fmaf(S.h1, Whl[1][3], fmaf(S.h0, Whl[0][3], zx.w));
    bb = fmaf(S.h3, Whl[3][3], S.h2 * Whl[2][3]);
    float q3 = __cosf(a + bb);

    // branch-free prefix product across the 4-lane group, per gate
    float a0s = __shfl_sync(0xffffffffu, q0, 0, 4);
    float a1s = __shfl_sync(0xffffffffu, q0, 1, 4);
    float a2s = __shfl_sync(0xffffffffu, q0, 2, 4);
    float b0s = __shfl_sync(0xffffffffu, q1, 0, 4);
    float b1s = __shfl_sync(0xffffffffu, q1, 1, 4);
    float b2s = __shfl_sync(0xffffffffu, q1, 2, 4);
    float c0s = __shfl_sync(0xffffffffu, q2, 0, 4);
    float c1s = __shfl_sync(0xffffffffu, q2, 1, 4);
    float c2s = __shfl_sync(0xffffffffu, q2, 2, 4);
    float d0s = __shfl_sync(0xffffffffu, q3, 0, 4);
    float d1s = __shfl_sync(0xffffffffu, q3, 1, 4);
    float d2s = __shfl_sync(0xffffffffu, q3, 2, 4);

    float m1 = ge1 ? a0s : 1.0f;
    float m2 = ge2 ? a1s : 1.0f;
    float m3 = ge3 ? a2s : 1.0f;
    float P0 = (q0 * m1) * (m2 * m3);
    m1 = ge1 ? b0s : 1.0f;
    m2 = ge2 ? b1s : 1.0f;
    m3 = ge3 ? b2s : 1.0f;
    float P1 = (q1 * m1) * (m2 * m3);
    m1 = ge1 ? c0s : 1.0f;
    m2 = ge2 ? c1s : 1.0f;
    m3 = ge3 ? c2s : 1.0f;
    float P2 = (q2 * m1) * (m2 * m3);
    m1 = ge1 ? d0s : 1.0f;
    m2 = ge2 ? d1s : 1.0f;
    m3 = ge3 ? d2s : 1.0f;
    float P3 = (q3 * m1) * (m2 * m3);

    float f  = sigp(P0);
    float i  = sigp(P1);
    float gg = tanh_cf_fast(P2);
    float o  = sigp(P3);

    S.c = fmaf(f, S.c, i * gg);
    float hu = o * tanh_cf_fast(S.c);
    hu_out = hu;

    S.h0 = __shfl_sync(0xffffffffu, hu, 0, 4);
    S.h1 = __shfl_sync(0xffffffffu, hu, 1, 4);
    S.h2 = __shfl_sync(0xffffffffu, hu, 2, 4);
    S.h3 = __shfl_sync(0xffffffffu, hu, 3, 4);
}

__global__ __launch_bounds__(32)
void recur_kernel(const float* __restrict__ Wf, const float* __restrict__ Wi,
                  const float* __restrict__ Wu, const float* __restrict__ Wo,
                  float* __restrict__ out)
{
    const int lane = threadIdx.x;
    const int u    = lane & 3;
    const int gidx = lane >> 2;                       // 0..7
    const int bA   = blockIdx.x * 16 + gidx;          // chain A batch element
    const int bB   = bA + 8;                          // chain B batch element

    // Whl[m][g] = W_gate_g[(128+m)*4 + u]  (shared by both chains)
    float Whl[4][4];
    #pragma unroll
    for (int m = 0; m < 4; m++) {
        Whl[m][0] = Wf[(128 + m) * 4 + u];
        Whl[m][1] = Wi[(128 + m) * 4 + u];
        Whl[m][2] = Wu[(128 + m) * 4 + u];
        Whl[m][3] = Wo[(128 + m) * 4 + u];
    }
    const bool ge1 = (u >= 1);
    const bool ge2 = (u >= 2);
    const bool ge3 = (u >= 3);

    Chain A, B;
    A.h0 = A.h1 = A.h2 = A.h3 = A.c = 0.f;
    B.h0 = B.h1 = B.h2 = B.h3 = B.c = 0.f;
    A.xp = (const float4*)g_xproj + ((size_t)bA * 4 + u);
    B.xp = (const float4*)g_xproj + ((size_t)bB * 4 + u);
    #pragma unroll
    for (int d = 0; d < RDEPTH; d++) {
        A.buf[d] = A.xp[(size_t)d * (BATCH * 4)];
        B.buf[d] = B.xp[(size_t)d * (BATCH * 4)];
    }

    #pragma unroll 2
    for (int t = 0; t < T_STEPS; t++) {
        const int slot = t & (RDEPTH - 1);
        float huA, huB;
        chain_step(A, t, slot, Whl, ge1, ge2, ge3, huA);
        chain_step(B, t, slot, Whl, ge1, ge2, ge3, huB);
        out[((size_t)t * BATCH + bA) * 4 + u] = huA;
        out[((size_t)t * BATCH + bB) * 4 + u] = huB;
    }

    // hx, cx appended after outputs
    float hxA = (u == 0) ? A.h0 : (u == 1) ? A.h1 : (u == 2) ? A.h2 : A.h3;
    float hxB = (u == 0) ? B.h0 : (u == 1) ? B.h1 : (u == 2) ? B.h2 : B.h3;
    size_t baseH = (size_t)T_STEPS * BATCH * 4;
    size_t baseC = baseH + (size_t)BATCH * 4;
    out[baseH + (size_t)bA * 4 + u] = hxA;
    out[baseH + (size_t)bB * 4 + u] = hxB;
    out[baseC + (size_t)bA * 4 + u] = A.c;
    out[baseC + (size_t)bB * 4 + u] = B.c;
}

// ---------------------------------------------------------------------------
extern "C" void kernel_launch(void* const* d_in, const int* in_sizes, int n_in,
                              void* d_out, int out_size)
{
    (void)in_sizes; (void)n_in; (void)out_size;
    const float* x   = (const float*)d_in[0];
    const float* Wf  = (const float*)d_in[1];
    const float* bf  = (const float*)d_in[2];
    const float* thf = (const float*)d_in[3];
    const float* Wi  = (const float*)d_in[4];
    const float* bi  = (const float*)d_in[5];
    const float* thi = (const float*)d_in[6];
    const float* Wu  = (const float*)d_in[7];
    const float* bu  = (const float*)d_in[8];
    const float* thu = (const float*)d_in[9];
    const float* Wo  = (const float*)d_in[10];
    const float* bo  = (const float*)d_in[11];
    const float* tho = (const float*)d_in[12];
    float* out = (float*)d_out;

    proj_kernel<<<(T_STEPS * BATCH) / TILE_ROWS, PROJ_THREADS>>>(
        x, Wf, bf, thf, Wi, bi, thi, Wu, bu, thu, Wo, bo, tho);
    recur_kernel<<<BATCH / 16, 32>>>(Wf, Wi, Wu, Wo, out);
}